// round 13
// baseline (speedup 1.0000x reference)
#include <cuda_runtime.h>
#include <cuda_bf16.h>
#include <cstdint>

#define BATCH  131072
#define FEAT   32
#define DEG    16
#define CLS    64
#define GRIDK  8
#define TBROWS 128          // rows per block
#define NTHR   1024         // 32 warps
#define NKT    16           // K=256 / 16 per MMA

// ---- dynamic smem byte offsets ----
#define OFF_FLAG    0
#define OFF_PAR     64                        // float params
#define PAR_WT      0                         // [d][f] 512 floats
#define PAR_INV     512
#define PAR_CP      544
#define PAR_SP      560
#define PAR_SC      576
#define PAR_BI      608
#define PAR_KB      640                       // 64 floats
#define OFF_A_HI    4096                      // [128][256] bf16, 512B rows, chunk^row swizzle
#define OFF_A_LO    (OFF_A_HI + 65536)
#define OFF_B_HI    (OFF_A_LO + 65536)        // [64][256] bf16
#define OFF_B_LO    (OFF_B_HI + 32768)
#define SMEM_TOTAL  (OFF_B_LO + 32768)        // 200704 B

static __device__ __forceinline__ uint32_t smem_u32(const void* p) {
    uint32_t a;
    asm("{ .reg .u64 t; cvta.to.shared.u64 t, %1; cvt.u32.u64 %0, t; }" : "=r"(a) : "l"(p));
    return a;
}
static __device__ __forceinline__ void ldsm4(uint32_t& r0, uint32_t& r1, uint32_t& r2,
                                             uint32_t& r3, uint32_t addr) {
    asm volatile("ldmatrix.sync.aligned.m8n8.x4.shared.b16 {%0,%1,%2,%3}, [%4];"
                 : "=r"(r0), "=r"(r1), "=r"(r2), "=r"(r3) : "r"(addr));
}
static __device__ __forceinline__ void mma_bf16(float* c, const uint32_t* a,
                                                const uint32_t* b) {
    asm volatile("mma.sync.aligned.m16n8k16.row.col.f32.bf16.bf16.f32 "
                 "{%0,%1,%2,%3}, {%4,%5,%6,%7}, {%8,%9}, {%0,%1,%2,%3};"
                 : "+f"(c[0]), "+f"(c[1]), "+f"(c[2]), "+f"(c[3])
                 : "r"(a[0]), "r"(a[1]), "r"(a[2]), "r"(a[3]), "r"(b[0]), "r"(b[1]));
}
// fast tanh: (e^2x - 1)/(e^2x + 1); arg bounded (|sc*lcu+bi| <~ 2.5) so no overflow.
static __device__ __forceinline__ float tanh_fast(float x) {
    const float e2x = exp2f(x * 2.8853900817779268f);   // e^(2x)
    return (e2x - 1.0f) * __frcp_rn(e2x + 1.0f);
}
// split pair (f0,f1) -> bf16x2 hi + bf16x2 lo
static __device__ __forceinline__ void split_pair(float f0, float f1,
                                                  uint32_t& hi, uint32_t& lo) {
    const __nv_bfloat162 h = __floats2bfloat162_rn(f0, f1);
    hi = *reinterpret_cast<const uint32_t*>(&h);
    const float h0 = __uint_as_float(hi << 16);          // low bf16 -> f32
    const float h1 = __uint_as_float(hi & 0xFFFF0000u);  // high bf16 -> f32
    const __nv_bfloat162 l = __floats2bfloat162_rn(f0 - h0, f1 - h1);
    lo = *reinterpret_cast<const uint32_t*>(&l);
}

__global__ __launch_bounds__(NTHR)
void qkan_mma_kernel(const float* __restrict__ X,
                     const float* __restrict__ phases,
                     const float* __restrict__ lcu_w,
                     const float* __restrict__ cand0,
                     const float* __restrict__ cand1,
                     const float* __restrict__ kan_coeff,
                     const float* __restrict__ kan_bias,
                     float* __restrict__ out) {
    extern __shared__ char smc[];
    float* par = (float*)(smc + OFF_PAR);

    const int t    = threadIdx.x;
    const int wid  = t >> 5;
    const int lane = t & 31;
    const int row0 = blockIdx.x * TBROWS;
    const uint32_t smem_base = smem_u32(smc);
    const float CLIPF = (float)(1.0 - 1e-6);

    // ---- scale/bias disambiguation (scale mean ~1 > bias mean ~0) ----
    if (t == 0) {
        float s0 = 0.f, s1 = 0.f;
        for (int i = 0; i < 32; i++) { s0 += cand0[i]; s1 += cand1[i]; }
        *(int*)(smc + OFF_FLAG) = (s0 > s1) ? 1 : 0;
    }
    __syncthreads();
    const int flag = *(const int*)(smc + OFF_FLAG);

    // ---- parameter staging (cooperatively written) ----
    if (t < DEG * FEAT) {                              // lcu_w [f][d] -> wT [d][f]
        const int f = t >> 4, d = t & 15;
        par[PAR_WT + d * 32 + f] = lcu_w[t];
    }
    if (t < 32) {
        float denom = 1e-6f;
#pragma unroll
        for (int d = 0; d < DEG; d++) denom += fabsf(lcu_w[t * DEG + d]);
        par[PAR_INV + t] = 1.0f / denom;
        par[PAR_SC + t] = flag ? cand0[t] : cand1[t];
        par[PAR_BI + t] = flag ? cand1[t] : cand0[t];
    }
    if (t < 16) {
        float sv, cv;
        sincosf(phases[t], &sv, &cv);
        par[PAR_CP + t] = cv;
        par[PAR_SP + t] = sv;
    }
    if (t < 64) par[PAR_KB + t] = kan_bias[t];

    // ---- B tiles: kan_coeff [c][256] -> bf16 hi/lo, 512B rows, chunk^(c&7) swizzle ----
#pragma unroll
    for (int it = 0; it < 2; it++) {
        const int j = t + NTHR * it;         // 2048 chunks of 8 floats
        const int c = j >> 5;                // class row 0..63
        const int q = j & 31;                // 16B chunk within row
        const float4* gp = (const float4*)(kan_coeff + c * 256 + q * 8);
        const float4 v0 = gp[0];
        const float4 v1 = gp[1];
        uint32_t hi[4], lo[4];
        split_pair(v0.x, v0.y, hi[0], lo[0]);
        split_pair(v0.z, v0.w, hi[1], lo[1]);
        split_pair(v1.x, v1.y, hi[2], lo[2]);
        split_pair(v1.z, v1.w, hi[3], lo[3]);
        const uint32_t off = (uint32_t)(c * 512 + ((q ^ (c & 7)) << 4));
        *(uint4*)(smc + OFF_B_HI + off) = make_uint4(hi[0], hi[1], hi[2], hi[3]);
        *(uint4*)(smc + OFF_B_LO + off) = make_uint4(lo[0], lo[1], lo[2], lo[3]);
    }

    // params cooperatively written above, read by stage-1 below: barrier required.
    __syncthreads();

    // ---- stage 1 (verified R4 math) + Chebyshev basis -> A hi/lo bf16 tiles ----
    {
        const int f   = t & 31;
        const int w32 = t >> 5;              // 0..31
        const float invd = par[PAR_INV + f];
        const float sc   = par[PAR_SC + f];
        const float bi   = par[PAR_BI + f];
#pragma unroll 2
        for (int i = 0; i < TBROWS / 32; i++) {
            const int r = w32 + 32 * i;
            float x = X[(size_t)(row0 + r) * FEAT + f];
            x = fminf(fmaxf(x, -CLIPF), CLIPF);
            const float sn = sqrtf(fmaf(-x, x, 1.0f));
            float c = x, s = sn, num = 0.f;
#pragma unroll
            for (int d = 0; d < DEG; d++) {
                const float q = fmaf(c, par[PAR_CP + d], -(s * par[PAR_SP + d]));
                num = fmaf(par[PAR_WT + d * 32 + f], q, num);
                const float cn = fmaf(-sn, s, c * x);
                s = fmaf(sn, c, s * x);
                c = cn;
            }
            float y = tanh_fast(fmaf(sc, num * invd, bi));
            y = fminf(fmaxf(y, -CLIPF), CLIPF);

            float T[GRIDK];
            T[0] = 1.0f; T[1] = y;
            const float y2 = y + y;
#pragma unroll
            for (int k = 2; k < GRIDK; k++) T[k] = fmaf(y2, T[k - 1], -T[k - 2]);

            uint32_t hi[4], lo[4];
            split_pair(T[0], T[1], hi[0], lo[0]);
            split_pair(T[2], T[3], hi[1], lo[1]);
            split_pair(T[4], T[5], hi[2], lo[2]);
            split_pair(T[6], T[7], hi[3], lo[3]);
            const uint32_t off = (uint32_t)(r * 512 + ((f ^ (r & 7)) << 4));
            *(uint4*)(smc + OFF_A_HI + off) = make_uint4(hi[0], hi[1], hi[2], hi[3]);
            *(uint4*)(smc + OFF_A_LO + off) = make_uint4(lo[0], lo[1], lo[2], lo[3]);
        }
    }
    __syncthreads();

    // ---- MMA phase: 32 warps, warp tile m16 x n16 (mt = wid>>2, nq = wid&3) ----
    {
        const int mt = wid >> 2;                                 // 0..7 -> rows mt*16..+15
        const int nq = wid & 3;                                  // 0..3 -> cols nq*16..+15
        const int lr   = lane & 7;
        const int a_cb = (lane >> 4) & 1;
        const int arow = mt * 16 + ((lane >> 3) & 1) * 8 + lr;
        const int b_cb = (lane >> 3) & 1;
        const int bn   = ((lane >> 4) & 1) * 8 + lr;

        const uint32_t aBaseHi = smem_base + OFF_A_HI + arow * 512;
        const uint32_t aBaseLo = smem_base + OFF_A_LO + arow * 512;
        const uint32_t bBase   = smem_base + OFF_B_HI + (nq * 16 + bn) * 512;

        float C[2][4];
#pragma unroll
        for (int n = 0; n < 2; n++)
#pragma unroll
            for (int j = 0; j < 4; j++) C[n][j] = 0.f;

#pragma unroll
        for (int kt = 0; kt < NKT; kt++) {
            const uint32_t offA = (uint32_t)(((kt * 2 + a_cb) ^ lr) << 4);
            const uint32_t offB = (uint32_t)(((kt * 2 + b_cb) ^ lr) << 4);
            uint32_t ah[4], al[4];
            ldsm4(ah[0], ah[1], ah[2], ah[3], aBaseHi + offA);
            ldsm4(al[0], al[1], al[2], al[3], aBaseLo + offA);
            uint32_t bh[2][2], bl[2][2];
            ldsm4(bh[0][0], bh[0][1], bh[1][0], bh[1][1], bBase + offB);
            ldsm4(bl[0][0], bl[0][1], bl[1][0], bl[1][1], bBase + 32768u + offB);
#pragma unroll
            for (int n = 0; n < 2; n++) {
                mma_bf16(C[n], ah, bh[n]);
                mma_bf16(C[n], al, bh[n]);
                mma_bf16(C[n], ah, bl[n]);
            }
        }

        // ---- epilogue: + kan_bias, float2 stores ----
        const int qrow = lane >> 2;            // 0..7
        const int col2 = 2 * (lane & 3);       // 0,2,4,6
        const int gr0 = row0 + mt * 16 + qrow;
#pragma unroll
        for (int n = 0; n < 2; n++) {
            const int col = nq * 16 + n * 8 + col2;
            const float kb0 = par[PAR_KB + col];
            const float kb1 = par[PAR_KB + col + 1];
            float2 v0, v1;
            v0.x = C[n][0] + kb0; v0.y = C[n][1] + kb1;
            v1.x = C[n][2] + kb0; v1.y = C[n][3] + kb1;
            *(float2*)(out + (size_t)gr0 * CLS + col) = v0;
            *(float2*)(out + (size_t)(gr0 + 8) * CLS + col) = v1;
        }
    }
}

extern "C" void kernel_launch(void* const* d_in, const int* in_sizes, int n_in,
                              void* d_out, int out_size) {
    int iX = 0, iP = 1, iW = 2, iC = 5, iKB = 6;
    int i32[2] = {3, 4};
    int n32 = 0;
    for (int i = 0; i < n_in; i++) {
        switch (in_sizes[i]) {
            case 4194304: iX = i; break;
            case 16:      iP = i; break;
            case 512:     iW = i; break;
            case 16384:   iC = i; break;
            case 64:      iKB = i; break;
            case 32:      if (n32 < 2) i32[n32] = i; n32++; break;
            default: break;
        }
    }

    const float* X      = (const float*)d_in[iX];
    const float* phases = (const float*)d_in[iP];
    const float* w      = (const float*)d_in[iW];
    const float* cand0  = (const float*)d_in[i32[0]];
    const float* cand1  = (const float*)d_in[i32[1]];
    const float* coeff  = (const float*)d_in[iC];
    const float* kbias  = (const float*)d_in[iKB];
    float* out          = (float*)d_out;

    cudaFuncSetAttribute(qkan_mma_kernel, cudaFuncAttributeMaxDynamicSharedMemorySize,
                         SMEM_TOTAL);
    qkan_mma_kernel<<<BATCH / TBROWS, NTHR, SMEM_TOTAL>>>(X, phases, w, cand0, cand1,
                                                          coeff, kbias, out);
}

// round 14
// speedup vs baseline: 1.2831x; 1.2831x over previous
#include <cuda_runtime.h>
#include <cuda_fp16.h>
#include <cstdint>

#define BATCH  131072
#define FEAT   32
#define DEG    16
#define CLS    64
#define GRIDK  8
#define TBROWS 64           // rows per block
#define NTHR   256          // 8 warps; 2 CTAs/SM
#define NKT    16           // K=256 / 16 per MMA

// ---- dynamic smem byte offsets (2 CTAs/SM: total must be <= ~113KB) ----
#define OFF_FLAG    0
#define OFF_PAR     64                        // float params
#define PAR_WT      0                         // [d][f] 512 floats
#define PAR_INV     512
#define PAR_CP      544
#define PAR_SP      560
#define PAR_SC      576
#define PAR_BI      608
#define PAR_KB      640                       // 64 floats
#define OFF_A_HI    4096                      // [64][256] fp16, 512B rows, chunk^row swizzle
#define OFF_A_LO    (OFF_A_HI + 32768)
#define OFF_B_HI    (OFF_A_LO + 32768)        // [64][256] fp16
#define SMEM_TOTAL  (OFF_B_HI + 32768)        // 102400 B (100KB)

static __device__ __forceinline__ uint32_t smem_u32(const void* p) {
    uint32_t a;
    asm("{ .reg .u64 t; cvta.to.shared.u64 t, %1; cvt.u32.u64 %0, t; }" : "=r"(a) : "l"(p));
    return a;
}
static __device__ __forceinline__ void ldsm4(uint32_t& r0, uint32_t& r1, uint32_t& r2,
                                             uint32_t& r3, uint32_t addr) {
    asm volatile("ldmatrix.sync.aligned.m8n8.x4.shared.b16 {%0,%1,%2,%3}, [%4];"
                 : "=r"(r0), "=r"(r1), "=r"(r2), "=r"(r3) : "r"(addr));
}
static __device__ __forceinline__ void mma_f16(float* c, const uint32_t* a,
                                               const uint32_t* b) {
    asm volatile("mma.sync.aligned.m16n8k16.row.col.f32.f16.f16.f32 "
                 "{%0,%1,%2,%3}, {%4,%5,%6,%7}, {%8,%9}, {%0,%1,%2,%3};"
                 : "+f"(c[0]), "+f"(c[1]), "+f"(c[2]), "+f"(c[3])
                 : "r"(a[0]), "r"(a[1]), "r"(a[2]), "r"(a[3]), "r"(b[0]), "r"(b[1]));
}
// fast tanh: (e^2x - 1)/(e^2x + 1); arg bounded so no overflow.
static __device__ __forceinline__ float tanh_fast(float x) {
    const float e2x = exp2f(x * 2.8853900817779268f);
    return (e2x - 1.0f) * __frcp_rn(e2x + 1.0f);
}
// fp16 pack of a float pair
static __device__ __forceinline__ uint32_t pack_h2(float f0, float f1) {
    const __half2 h = __floats2half2_rn(f0, f1);
    return *reinterpret_cast<const uint32_t*>(&h);
}
// split pair -> fp16x2 hi + fp16x2 lo (lo = exact residual, fp16-rounded)
static __device__ __forceinline__ void split_pair_h2(float f0, float f1,
                                                     uint32_t& hi, uint32_t& lo) {
    const __half2 h = __floats2half2_rn(f0, f1);
    hi = *reinterpret_cast<const uint32_t*>(&h);
    const float2 hf = __half22float2(h);
    const __half2 l = __floats2half2_rn(f0 - hf.x, f1 - hf.y);
    lo = *reinterpret_cast<const uint32_t*>(&l);
}

__global__ __launch_bounds__(NTHR, 2)
void qkan_mma_kernel(const float* __restrict__ X,
                     const float* __restrict__ phases,
                     const float* __restrict__ lcu_w,
                     const float* __restrict__ cand0,
                     const float* __restrict__ cand1,
                     const float* __restrict__ kan_coeff,
                     const float* __restrict__ kan_bias,
                     float* __restrict__ out) {
    extern __shared__ char smc[];
    float* par = (float*)(smc + OFF_PAR);

    const int t    = threadIdx.x;
    const int wid  = t >> 5;
    const int lane = t & 31;
    const int row0 = blockIdx.x * TBROWS;
    const uint32_t smem_base = smem_u32(smc);
    const float CLIPF = (float)(1.0 - 1e-6);

    // ---- scale/bias disambiguation (scale mean ~1 > bias mean ~0) ----
    if (t == 0) {
        float s0 = 0.f, s1 = 0.f;
        for (int i = 0; i < 32; i++) { s0 += cand0[i]; s1 += cand1[i]; }
        *(int*)(smc + OFF_FLAG) = (s0 > s1) ? 1 : 0;
    }
    __syncthreads();
    const int flag = *(const int*)(smc + OFF_FLAG);

    // ---- parameter staging (cooperatively written) ----
    for (int j = t; j < DEG * FEAT; j += NTHR) {       // lcu_w [f][d] -> wT [d][f]
        const int f = j >> 4, d = j & 15;
        par[PAR_WT + d * 32 + f] = lcu_w[j];
    }
    if (t < 32) {
        float denom = 1e-6f;
#pragma unroll
        for (int d = 0; d < DEG; d++) denom += fabsf(lcu_w[t * DEG + d]);
        par[PAR_INV + t] = 1.0f / denom;
        par[PAR_SC + t] = flag ? cand0[t] : cand1[t];
        par[PAR_BI + t] = flag ? cand1[t] : cand0[t];
    }
    if (t < 16) {
        float sv, cv;
        sincosf(phases[t], &sv, &cv);
        par[PAR_CP + t] = cv;
        par[PAR_SP + t] = sv;
    }
    if (t < 64) par[PAR_KB + t] = kan_bias[t];

    // ---- B tile: kan_coeff [c][256] -> fp16 (hi only), 512B rows, chunk^(c&7) swizzle ----
#pragma unroll
    for (int it = 0; it < 8; it++) {
        const int j = t + NTHR * it;         // 2048 chunks of 8 floats
        const int c = j >> 5;                // class row 0..63
        const int q = j & 31;                // 16B chunk within row
        const float4* gp = (const float4*)(kan_coeff + c * 256 + q * 8);
        const float4 v0 = gp[0];
        const float4 v1 = gp[1];
        const uint32_t h0 = pack_h2(v0.x, v0.y);
        const uint32_t h1 = pack_h2(v0.z, v0.w);
        const uint32_t h2 = pack_h2(v1.x, v1.y);
        const uint32_t h3 = pack_h2(v1.z, v1.w);
        const uint32_t off = (uint32_t)(c * 512 + ((q ^ (c & 7)) << 4));
        *(uint4*)(smc + OFF_B_HI + off) = make_uint4(h0, h1, h2, h3);
    }

    // params cooperatively written above, read by stage-1 below: barrier required.
    __syncthreads();

    // ---- stage 1 (verified R4 math) + Chebyshev basis -> A hi/lo fp16 tiles ----
    {
        const int f  = t & 31;
        const int w8 = t >> 5;               // 0..7
        const float invd = par[PAR_INV + f];
        const float sc   = par[PAR_SC + f];
        const float bi   = par[PAR_BI + f];
#pragma unroll 2
        for (int i = 0; i < TBROWS / 8; i++) {
            const int r = w8 + 8 * i;
            float x = X[(size_t)(row0 + r) * FEAT + f];
            x = fminf(fmaxf(x, -CLIPF), CLIPF);
            const float sn = sqrtf(fmaf(-x, x, 1.0f));
            float c = x, s = sn, num = 0.f;
#pragma unroll
            for (int d = 0; d < DEG; d++) {
                const float q = fmaf(c, par[PAR_CP + d], -(s * par[PAR_SP + d]));
                num = fmaf(par[PAR_WT + d * 32 + f], q, num);
                const float cn = fmaf(-sn, s, c * x);
                s = fmaf(sn, c, s * x);
                c = cn;
            }
            float y = tanh_fast(fmaf(sc, num * invd, bi));
            y = fminf(fmaxf(y, -CLIPF), CLIPF);

            float T[GRIDK];
            T[0] = 1.0f; T[1] = y;
            const float y2 = y + y;
#pragma unroll
            for (int k = 2; k < GRIDK; k++) T[k] = fmaf(y2, T[k - 1], -T[k - 2]);

            uint32_t hi[4], lo[4];
            split_pair_h2(T[0], T[1], hi[0], lo[0]);
            split_pair_h2(T[2], T[3], hi[1], lo[1]);
            split_pair_h2(T[4], T[5], hi[2], lo[2]);
            split_pair_h2(T[6], T[7], hi[3], lo[3]);
            const uint32_t off = (uint32_t)(r * 512 + ((f ^ (r & 7)) << 4));
            *(uint4*)(smc + OFF_A_HI + off) = make_uint4(hi[0], hi[1], hi[2], hi[3]);
            *(uint4*)(smc + OFF_A_LO + off) = make_uint4(lo[0], lo[1], lo[2], lo[3]);
        }
    }
    __syncthreads();

    // ---- MMA phase: 8 warps, warp tile m16 x n32 (R11-validated mapping, fp16, 2-pass) ----
    {
        const int mt    = wid >> 1;                              // 0..3 -> rows mt*16..+15
        const int nhalf = wid & 1;                               // 0..1 -> cols nhalf*32..+31
        const int lr   = lane & 7;
        const int a_cb = (lane >> 4) & 1;
        const int arow = mt * 16 + ((lane >> 3) & 1) * 8 + lr;
        const int b_cb = (lane >> 3) & 1;
        const int bn   = ((lane >> 4) & 1) * 8 + lr;

        const uint32_t aBaseHi = smem_base + OFF_A_HI + arow * 512;
        const uint32_t aBaseLo = smem_base + OFF_A_LO + arow * 512;
        uint32_t bBase[2];
#pragma unroll
        for (int p = 0; p < 2; p++)
            bBase[p] = smem_base + OFF_B_HI + ((nhalf * 2 + p) * 16 + bn) * 512;

        float C[4][4];
#pragma unroll
        for (int n = 0; n < 4; n++)
#pragma unroll
            for (int j = 0; j < 4; j++) C[n][j] = 0.f;

#pragma unroll
        for (int kt = 0; kt < NKT; kt++) {
            const uint32_t offA = (uint32_t)(((kt * 2 + a_cb) ^ lr) << 4);
            const uint32_t offB = (uint32_t)(((kt * 2 + b_cb) ^ lr) << 4);
            uint32_t ah[4], al[4];
            ldsm4(ah[0], ah[1], ah[2], ah[3], aBaseHi + offA);
            ldsm4(al[0], al[1], al[2], al[3], aBaseLo + offA);
            uint32_t bh[4][2];
#pragma unroll
            for (int p = 0; p < 2; p++)
                ldsm4(bh[2 * p][0], bh[2 * p][1], bh[2 * p + 1][0], bh[2 * p + 1][1],
                      bBase[p] + offB);
#pragma unroll
            for (int n = 0; n < 4; n++) {
                mma_f16(C[n], ah, bh[n]);
                mma_f16(C[n], al, bh[n]);
            }
        }

        // ---- epilogue: + kan_bias, float2 stores ----
        const int qrow = lane >> 2;            // 0..7
        const int col2 = 2 * (lane & 3);       // 0,2,4,6
        const int gr0 = row0 + mt * 16 + qrow;
#pragma unroll
        for (int n = 0; n < 4; n++) {
            const int col = nhalf * 32 + n * 8 + col2;
            const float kb0 = par[PAR_KB + col];
            const float kb1 = par[PAR_KB + col + 1];
            float2 v0, v1;
            v0.x = C[n][0] + kb0; v0.y = C[n][1] + kb1;
            v1.x = C[n][2] + kb0; v1.y = C[n][3] + kb1;
            *(float2*)(out + (size_t)gr0 * CLS + col) = v0;
            *(float2*)(out + (size_t)(gr0 + 8) * CLS + col) = v1;
        }
    }
}

extern "C" void kernel_launch(void* const* d_in, const int* in_sizes, int n_in,
                              void* d_out, int out_size) {
    int iX = 0, iP = 1, iW = 2, iC = 5, iKB = 6;
    int i32[2] = {3, 4};
    int n32 = 0;
    for (int i = 0; i < n_in; i++) {
        switch (in_sizes[i]) {
            case 4194304: iX = i; break;
            case 16:      iP = i; break;
            case 512:     iW = i; break;
            case 16384:   iC = i; break;
            case 64:      iKB = i; break;
            case 32:      if (n32 < 2) i32[n32] = i; n32++; break;
            default: break;
        }
    }

    const float* X      = (const float*)d_in[iX];
    const float* phases = (const float*)d_in[iP];
    const float* w      = (const float*)d_in[iW];
    const float* cand0  = (const float*)d_in[i32[0]];
    const float* cand1  = (const float*)d_in[i32[1]];
    const float* coeff  = (const float*)d_in[iC];
    const float* kbias  = (const float*)d_in[iKB];
    float* out          = (float*)d_out;

    cudaFuncSetAttribute(qkan_mma_kernel, cudaFuncAttributeMaxDynamicSharedMemorySize,
                         SMEM_TOTAL);
    qkan_mma_kernel<<<BATCH / TBROWS, NTHR, SMEM_TOTAL>>>(X, phases, w, cand0, cand1,
                                                          coeff, kbias, out);
}

// round 15
// speedup vs baseline: 1.6679x; 1.2998x over previous
#include <cuda_runtime.h>
#include <cuda_fp16.h>
#include <cstdint>

#define BATCH  131072
#define FEAT   32
#define DEG    16
#define CLS    64
#define GRIDK  8
#define TBROWS 64           // rows per block
#define NTHR   256          // 8 warps; 3 CTAs/SM
#define NKT    16           // K=256 / 16 per MMA

// ---- dynamic smem byte offsets (3 CTAs/SM: total <= ~75KB) ----
#define OFF_FLAG    0
#define OFF_PAR     64                        // float params
#define PAR_WT      0                         // [d][f] 512 floats
#define PAR_INV     512
#define PAR_CP      544
#define PAR_SP      560
#define PAR_SC      576
#define PAR_BI      608
#define PAR_KB      640                       // 64 floats
#define OFF_A       4096                      // [64][256] fp16, 512B rows, chunk^row swizzle
#define OFF_B       (OFF_A + 32768)           // [64][256] fp16 (pre-swizzled copy)
#define SMEM_TOTAL  (OFF_B + 32768)           // 69632 B (68KB)

// Pre-converted, pre-swizzled fp16 B tile (written once by prep kernel).
__device__ uint4 g_Bh[2048];                  // 32KB

static __device__ __forceinline__ uint32_t smem_u32(const void* p) {
    uint32_t a;
    asm("{ .reg .u64 t; cvta.to.shared.u64 t, %1; cvt.u32.u64 %0, t; }" : "=r"(a) : "l"(p));
    return a;
}
static __device__ __forceinline__ void ldsm4(uint32_t& r0, uint32_t& r1, uint32_t& r2,
                                             uint32_t& r3, uint32_t addr) {
    asm volatile("ldmatrix.sync.aligned.m8n8.x4.shared.b16 {%0,%1,%2,%3}, [%4];"
                 : "=r"(r0), "=r"(r1), "=r"(r2), "=r"(r3) : "r"(addr));
}
static __device__ __forceinline__ void mma_f16(float* c, const uint32_t* a,
                                               const uint32_t* b) {
    asm volatile("mma.sync.aligned.m16n8k16.row.col.f32.f16.f16.f32 "
                 "{%0,%1,%2,%3}, {%4,%5,%6,%7}, {%8,%9}, {%0,%1,%2,%3};"
                 : "+f"(c[0]), "+f"(c[1]), "+f"(c[2]), "+f"(c[3])
                 : "r"(a[0]), "r"(a[1]), "r"(a[2]), "r"(a[3]), "r"(b[0]), "r"(b[1]));
}
static __device__ __forceinline__ float tanh_fast(float x) {
    const float e2x = exp2f(x * 2.8853900817779268f);
    return (e2x - 1.0f) * __frcp_rn(e2x + 1.0f);
}
static __device__ __forceinline__ uint32_t pack_h2(float f0, float f1) {
    const __half2 h = __floats2half2_rn(f0, f1);
    return *reinterpret_cast<const uint32_t*>(&h);
}

// ---- prep: convert kan_coeff [c][256] f32 -> fp16, swizzled layout, once ----
__global__ void prep_b_kernel(const float* __restrict__ kan_coeff) {
    const int t = threadIdx.x;
#pragma unroll
    for (int it = 0; it < 8; it++) {
        const int j = t + 256 * it;          // 2048 chunks of 8 floats
        const int c = j >> 5;                // class row 0..63
        const int q = j & 31;                // 16B chunk within row
        const float4* gp = (const float4*)(kan_coeff + c * 256 + q * 8);
        const float4 v0 = gp[0];
        const float4 v1 = gp[1];
        uint4 o;
        o.x = pack_h2(v0.x, v0.y);
        o.y = pack_h2(v0.z, v0.w);
        o.z = pack_h2(v1.x, v1.y);
        o.w = pack_h2(v1.z, v1.w);
        g_Bh[c * 32 + (q ^ (c & 7))] = o;    // byte off = c*512 + ((q^(c&7))<<4)
    }
}

__global__ __launch_bounds__(NTHR, 3)
void qkan_mma_kernel(const float* __restrict__ X,
                     const float* __restrict__ phases,
                     const float* __restrict__ lcu_w,
                     const float* __restrict__ cand0,
                     const float* __restrict__ cand1,
                     const float* __restrict__ kan_bias,
                     float* __restrict__ out) {
    extern __shared__ char smc[];
    float* par = (float*)(smc + OFF_PAR);

    const int t    = threadIdx.x;
    const int wid  = t >> 5;
    const int lane = t & 31;
    const int row0 = blockIdx.x * TBROWS;
    const uint32_t smem_base = smem_u32(smc);
    const float CLIPF = (float)(1.0 - 1e-6);

    // ---- scale/bias disambiguation (scale mean ~1 > bias mean ~0) ----
    if (t == 0) {
        float s0 = 0.f, s1 = 0.f;
        for (int i = 0; i < 32; i++) { s0 += cand0[i]; s1 += cand1[i]; }
        *(int*)(smc + OFF_FLAG) = (s0 > s1) ? 1 : 0;
    }
    __syncthreads();
    const int flag = *(const int*)(smc + OFF_FLAG);

    // ---- parameter staging (cooperatively written) ----
    for (int j = t; j < DEG * FEAT; j += NTHR) {       // lcu_w [f][d] -> wT [d][f]
        const int f = j >> 4, d = j & 15;
        par[PAR_WT + d * 32 + f] = lcu_w[j];
    }
    if (t < 32) {
        float denom = 1e-6f;
#pragma unroll
        for (int d = 0; d < DEG; d++) denom += fabsf(lcu_w[t * DEG + d]);
        par[PAR_INV + t] = 1.0f / denom;
        par[PAR_SC + t] = flag ? cand0[t] : cand1[t];
        par[PAR_BI + t] = flag ? cand1[t] : cand0[t];
    }
    if (t < 16) {
        float sv, cv;
        sincosf(phases[t], &sv, &cv);
        par[PAR_CP + t] = cv;
        par[PAR_SP + t] = sv;
    }
    if (t < 64) par[PAR_KB + t] = kan_bias[t];

    // ---- B tile: straight 32KB copy of pre-converted, pre-swizzled fp16 ----
    {
        uint4* dst = (uint4*)(smc + OFF_B);
#pragma unroll
        for (int it = 0; it < 8; it++) {
            const int j = t + 256 * it;
            dst[j] = g_Bh[j];
        }
    }

    // params cooperatively written above, read by stage-1 below: barrier required.
    __syncthreads();

    // ---- stage 1 (verified R4 math) + Chebyshev basis -> A fp16 tile ----
    {
        const int f  = t & 31;
        const int w8 = t >> 5;               // 0..7
        const float invd = par[PAR_INV + f];
        const float sc   = par[PAR_SC + f];
        const float bi   = par[PAR_BI + f];
#pragma unroll 2
        for (int i = 0; i < TBROWS / 8; i++) {
            const int r = w8 + 8 * i;
            float x = X[(size_t)(row0 + r) * FEAT + f];
            x = fminf(fmaxf(x, -CLIPF), CLIPF);
            const float sn = sqrtf(fmaf(-x, x, 1.0f));
            float c = x, s = sn, num = 0.f;
#pragma unroll
            for (int d = 0; d < DEG; d++) {
                const float q = fmaf(c, par[PAR_CP + d], -(s * par[PAR_SP + d]));
                num = fmaf(par[PAR_WT + d * 32 + f], q, num);
                const float cn = fmaf(-sn, s, c * x);
                s = fmaf(sn, c, s * x);
                c = cn;
            }
            float y = tanh_fast(fmaf(sc, num * invd, bi));
            y = fminf(fmaxf(y, -CLIPF), CLIPF);

            float T[GRIDK];
            T[0] = 1.0f; T[1] = y;
            const float y2 = y + y;
#pragma unroll
            for (int k = 2; k < GRIDK; k++) T[k] = fmaf(y2, T[k - 1], -T[k - 2]);

            uint4 o;
            o.x = pack_h2(T[0], T[1]);
            o.y = pack_h2(T[2], T[3]);
            o.z = pack_h2(T[4], T[5]);
            o.w = pack_h2(T[6], T[7]);
            const uint32_t off = (uint32_t)(r * 512 + ((f ^ (r & 7)) << 4));
            *(uint4*)(smc + OFF_A + off) = o;
        }
    }
    __syncthreads();

    // ---- MMA phase: 8 warps, warp tile m16 x n32, single fp16 pass ----
    {
        const int mt    = wid >> 1;                              // 0..3 -> rows mt*16..+15
        const int nhalf = wid & 1;                               // 0..1 -> cols nhalf*32..+31
        const int lr   = lane & 7;
        const int a_cb = (lane >> 4) & 1;
        const int arow = mt * 16 + ((lane >> 3) & 1) * 8 + lr;
        const int b_cb = (lane >> 3) & 1;
        const int bn   = ((lane >> 4) & 1) * 8 + lr;

        const uint32_t aBase = smem_base + OFF_A + arow * 512;
        uint32_t bBase[2];
#pragma unroll
        for (int p = 0; p < 2; p++)
            bBase[p] = smem_base + OFF_B + ((nhalf * 2 + p) * 16 + bn) * 512;

        float C[4][4];
#pragma unroll
        for (int n = 0; n < 4; n++)
#pragma unroll
            for (int j = 0; j < 4; j++) C[n][j] = 0.f;

#pragma unroll
        for (int kt = 0; kt < NKT; kt++) {
            const uint32_t offA = (uint32_t)(((kt * 2 + a_cb) ^ lr) << 4);
            const uint32_t offB = (uint32_t)(((kt * 2 + b_cb) ^ lr) << 4);
            uint32_t ah[4];
            ldsm4(ah[0], ah[1], ah[2], ah[3], aBase + offA);
            uint32_t bh[4][2];
#pragma unroll
            for (int p = 0; p < 2; p++)
                ldsm4(bh[2 * p][0], bh[2 * p][1], bh[2 * p + 1][0], bh[2 * p + 1][1],
                      bBase[p] + offB);
#pragma unroll
            for (int n = 0; n < 4; n++)
                mma_f16(C[n], ah, bh[n]);
        }

        // ---- epilogue: + kan_bias, float2 stores ----
        const int qrow = lane >> 2;            // 0..7
        const int col2 = 2 * (lane & 3);       // 0,2,4,6
        const int gr0 = row0 + mt * 16 + qrow;
#pragma unroll
        for (int n = 0; n < 4; n++) {
            const int col = nhalf * 32 + n * 8 + col2;
            const float kb0 = par[PAR_KB + col];
            const float kb1 = par[PAR_KB + col + 1];
            float2 v0, v1;
            v0.x = C[n][0] + kb0; v0.y = C[n][1] + kb1;
            v1.x = C[n][2] + kb0; v1.y = C[n][3] + kb1;
            *(float2*)(out + (size_t)gr0 * CLS + col) = v0;
            *(float2*)(out + (size_t)(gr0 + 8) * CLS + col) = v1;
        }
    }
}

extern "C" void kernel_launch(void* const* d_in, const int* in_sizes, int n_in,
                              void* d_out, int out_size) {
    int iX = 0, iP = 1, iW = 2, iC = 5, iKB = 6;
    int i32[2] = {3, 4};
    int n32 = 0;
    for (int i = 0; i < n_in; i++) {
        switch (in_sizes[i]) {
            case 4194304: iX = i; break;
            case 16:      iP = i; break;
            case 512:     iW = i; break;
            case 16384:   iC = i; break;
            case 64:      iKB = i; break;
            case 32:      if (n32 < 2) i32[n32] = i; n32++; break;
            default: break;
        }
    }

    const float* X      = (const float*)d_in[iX];
    const float* phases = (const float*)d_in[iP];
    const float* w      = (const float*)d_in[iW];
    const float* cand0  = (const float*)d_in[i32[0]];
    const float* cand1  = (const float*)d_in[i32[1]];
    const float* coeff  = (const float*)d_in[iC];
    const float* kbias  = (const float*)d_in[iKB];
    float* out          = (float*)d_out;

    cudaFuncSetAttribute(qkan_mma_kernel, cudaFuncAttributeMaxDynamicSharedMemorySize,
                         SMEM_TOTAL);
    prep_b_kernel<<<1, 256>>>(coeff);
    qkan_mma_kernel<<<BATCH / TBROWS, NTHR, SMEM_TOTAL>>>(X, phases, w, cand0, cand1,
                                                          kbias, out);
}

// round 16
// speedup vs baseline: 1.7263x; 1.0350x over previous
#include <cuda_runtime.h>
#include <cuda_fp16.h>
#include <cstdint>

#define BATCH  131072
#define FEAT   32
#define DEG    16
#define CLS    64
#define GRIDK  8
#define TBROWS 64           // rows per block
#define NTHR   256          // 8 warps; 3 CTAs/SM
#define NKT    16           // K=256 / 16 per MMA

// ---- dynamic smem byte offsets (3 CTAs/SM: total <= ~75KB) ----
#define OFF_FLAG    0
#define OFF_PAR     64                        // float params
#define PAR_CW      0                         // [d][f] w*cos(phi) 512 floats
#define PAR_SW      512                       // [d][f] w*sin(phi) 512 floats
#define PAR_INV     1024                      // 32
#define PAR_SC      1056                      // 32
#define PAR_BI      1088                      // 32
#define PAR_KB      1120                      // 64 -> ends 1184
#define OFF_A       8192                      // [64][256] fp16, 512B rows, chunk^row swizzle
#define OFF_B       (OFF_A + 32768)           // [64][256] fp16 (pre-swizzled copy)
#define SMEM_TOTAL  (OFF_B + 32768)           // 73728 B (72KB)

// Pre-converted, pre-swizzled fp16 B tile (written once by prep kernel).
__device__ uint4 g_Bh[2048];                  // 32KB

static __device__ __forceinline__ uint32_t smem_u32(const void* p) {
    uint32_t a;
    asm("{ .reg .u64 t; cvta.to.shared.u64 t, %1; cvt.u32.u64 %0, t; }" : "=r"(a) : "l"(p));
    return a;
}
static __device__ __forceinline__ void ldsm4(uint32_t& r0, uint32_t& r1, uint32_t& r2,
                                             uint32_t& r3, uint32_t addr) {
    asm volatile("ldmatrix.sync.aligned.m8n8.x4.shared.b16 {%0,%1,%2,%3}, [%4];"
                 : "=r"(r0), "=r"(r1), "=r"(r2), "=r"(r3) : "r"(addr));
}
static __device__ __forceinline__ void mma_f16(float* c, const uint32_t* a,
                                               const uint32_t* b) {
    asm volatile("mma.sync.aligned.m16n8k16.row.col.f32.f16.f16.f32 "
                 "{%0,%1,%2,%3}, {%4,%5,%6,%7}, {%8,%9}, {%0,%1,%2,%3};"
                 : "+f"(c[0]), "+f"(c[1]), "+f"(c[2]), "+f"(c[3])
                 : "r"(a[0]), "r"(a[1]), "r"(a[2]), "r"(a[3]), "r"(b[0]), "r"(b[1]));
}
static __device__ __forceinline__ float tanh_fast(float x) {
    const float e2x = exp2f(x * 2.8853900817779268f);
    return (e2x - 1.0f) * __frcp_rn(e2x + 1.0f);
}
static __device__ __forceinline__ uint32_t pack_h2(float f0, float f1) {
    const __half2 h = __floats2half2_rn(f0, f1);
    return *reinterpret_cast<const uint32_t*>(&h);
}

// ---- prep: convert kan_coeff [c][256] f32 -> fp16, swizzled layout, once ----
__global__ void prep_b_kernel(const float* __restrict__ kan_coeff) {
    const int t = threadIdx.x;
#pragma unroll
    for (int it = 0; it < 8; it++) {
        const int j = t + 256 * it;          // 2048 chunks of 8 floats
        const int c = j >> 5;                // class row 0..63
        const int q = j & 31;                // 16B chunk within row
        const float4* gp = (const float4*)(kan_coeff + c * 256 + q * 8);
        const float4 v0 = gp[0];
        const float4 v1 = gp[1];
        uint4 o;
        o.x = pack_h2(v0.x, v0.y);
        o.y = pack_h2(v0.z, v0.w);
        o.z = pack_h2(v1.x, v1.y);
        o.w = pack_h2(v1.z, v1.w);
        g_Bh[c * 32 + (q ^ (c & 7))] = o;
    }
}

__global__ __launch_bounds__(NTHR, 3)
void qkan_mma_kernel(const float* __restrict__ X,
                     const float* __restrict__ phases,
                     const float* __restrict__ lcu_w,
                     const float* __restrict__ cand0,
                     const float* __restrict__ cand1,
                     const float* __restrict__ kan_bias,
                     float* __restrict__ out) {
    extern __shared__ char smc[];
    float* par = (float*)(smc + OFF_PAR);

    const int t    = threadIdx.x;
    const int wid  = t >> 5;
    const int lane = t & 31;
    const int row0 = blockIdx.x * TBROWS;
    const uint32_t smem_base = smem_u32(smc);
    const float CLIPF = (float)(1.0 - 1e-6);

    // ---- scale/bias disambiguation (scale mean ~1 > bias mean ~0) ----
    if (t == 0) {
        float s0 = 0.f, s1 = 0.f;
        for (int i = 0; i < 32; i++) { s0 += cand0[i]; s1 += cand1[i]; }
        *(int*)(smc + OFF_FLAG) = (s0 > s1) ? 1 : 0;
    }
    __syncthreads();
    const int flag = *(const int*)(smc + OFF_FLAG);

    // ---- parameter staging (cooperatively written) ----
    // cw[d][f] = w[f][d]*cos(phi_d), sw[d][f] = w[f][d]*sin(phi_d)
    for (int j = t; j < DEG * FEAT; j += NTHR) {
        const int f = j >> 4, d = j & 15;
        float sv, cv;
        sincosf(phases[d], &sv, &cv);
        const float w = lcu_w[j];
        par[PAR_CW + d * 32 + f] = w * cv;
        par[PAR_SW + d * 32 + f] = w * sv;
    }
    if (t < 32) {
        float denom = 1e-6f;
#pragma unroll
        for (int d = 0; d < DEG; d++) denom += fabsf(lcu_w[t * DEG + d]);
        par[PAR_INV + t] = 1.0f / denom;
        par[PAR_SC + t] = flag ? cand0[t] : cand1[t];
        par[PAR_BI + t] = flag ? cand1[t] : cand0[t];
    }
    if (t < 64) par[PAR_KB + t] = kan_bias[t];

    // ---- B tile: straight 32KB copy of pre-converted, pre-swizzled fp16 ----
    {
        uint4* dst = (uint4*)(smc + OFF_B);
#pragma unroll
        for (int it = 0; it < 8; it++) {
            const int j = t + 256 * it;
            dst[j] = g_Bh[j];
        }
    }

    // params cooperatively written above, read by stage-1 below: barrier required.
    __syncthreads();

    // ---- stage 1 via Chebyshev T/U (exact identity):
    //      cos(d*th + phi_d) = T_d(x)*cos(phi_d) - sin(th)*U_{d-1}(x)*sin(phi_d) ----
    {
        const int f  = t & 31;
        const int w8 = t >> 5;               // 0..7
        const float invd = par[PAR_INV + f];
        const float sc   = par[PAR_SC + f];
        const float bi   = par[PAR_BI + f];
#pragma unroll 4
        for (int i = 0; i < TBROWS / 8; i++) {
            const int r = w8 + 8 * i;
            float x = X[(size_t)(row0 + r) * FEAT + f];
            x = fminf(fmaxf(x, -CLIPF), CLIPF);
            const float sn = sqrtf(fmaf(-x, x, 1.0f));   // sin(theta) >= 0
            const float x2 = x + x;
            float Tp = x, Tpp = 1.0f;                    // T_1, T_0
            float Up = 1.0f, Upp = 0.0f;                 // U_0, U_{-1}
            float accT = 0.f, accU = 0.f;
#pragma unroll
            for (int d = 0; d < DEG; d++) {
                accT = fmaf(par[PAR_CW + d * 32 + f], Tp, accT);   // uses T_{d+1}
                accU = fmaf(par[PAR_SW + d * 32 + f], Up, accU);   // uses U_d
                const float Tn = fmaf(x2, Tp, -Tpp); Tpp = Tp; Tp = Tn;
                const float Un = fmaf(x2, Up, -Upp); Upp = Up; Up = Un;
            }
            const float num = fmaf(-sn, accU, accT);
            float y = tanh_fast(fmaf(sc, num * invd, bi));
            y = fminf(fmaxf(y, -CLIPF), CLIPF);

            float T[GRIDK];
            T[0] = 1.0f; T[1] = y;
            const float y2 = y + y;
#pragma unroll
            for (int k = 2; k < GRIDK; k++) T[k] = fmaf(y2, T[k - 1], -T[k - 2]);

            uint4 o;
            o.x = pack_h2(T[0], T[1]);
            o.y = pack_h2(T[2], T[3]);
            o.z = pack_h2(T[4], T[5]);
            o.w = pack_h2(T[6], T[7]);
            const uint32_t off = (uint32_t)(r * 512 + ((f ^ (r & 7)) << 4));
            *(uint4*)(smc + OFF_A + off) = o;
        }
    }
    __syncthreads();

    // ---- MMA phase: 8 warps, warp tile m16 x n32, single fp16 pass ----
    {
        const int mt    = wid >> 1;                              // 0..3 -> rows mt*16..+15
        const int nhalf = wid & 1;                               // 0..1 -> cols nhalf*32..+31
        const int lr   = lane & 7;
        const int a_cb = (lane >> 4) & 1;
        const int arow = mt * 16 + ((lane >> 3) & 1) * 8 + lr;
        const int b_cb = (lane >> 3) & 1;
        const int bn   = ((lane >> 4) & 1) * 8 + lr;

        const uint32_t aBase = smem_base + OFF_A + arow * 512;
        uint32_t bBase[2];
#pragma unroll
        for (int p = 0; p < 2; p++)
            bBase[p] = smem_base + OFF_B + ((nhalf * 2 + p) * 16 + bn) * 512;

        float C[4][4];
#pragma unroll
        for (int n = 0; n < 4; n++)
#pragma unroll
            for (int j = 0; j < 4; j++) C[n][j] = 0.f;

#pragma unroll
        for (int kt = 0; kt < NKT; kt++) {
            const uint32_t offA = (uint32_t)(((kt * 2 + a_cb) ^ lr) << 4);
            const uint32_t offB = (uint32_t)(((kt * 2 + b_cb) ^ lr) << 4);
            uint32_t ah[4];
            ldsm4(ah[0], ah[1], ah[2], ah[3], aBase + offA);
            uint32_t bh[4][2];
#pragma unroll
            for (int p = 0; p < 2; p++)
                ldsm4(bh[2 * p][0], bh[2 * p][1], bh[2 * p + 1][0], bh[2 * p + 1][1],
                      bBase[p] + offB);
#pragma unroll
            for (int n = 0; n < 4; n++)
                mma_f16(C[n], ah, bh[n]);
        }

        // ---- epilogue: + kan_bias, float2 stores ----
        const int qrow = lane >> 2;            // 0..7
        const int col2 = 2 * (lane & 3);       // 0,2,4,6
        const int gr0 = row0 + mt * 16 + qrow;
#pragma unroll
        for (int n = 0; n < 4; n++) {
            const int col = nhalf * 32 + n * 8 + col2;
            const float kb0 = par[PAR_KB + col];
            const float kb1 = par[PAR_KB + col + 1];
            float2 v0, v1;
            v0.x = C[n][0] + kb0; v0.y = C[n][1] + kb1;
            v1.x = C[n][2] + kb0; v1.y = C[n][3] + kb1;
            *(float2*)(out + (size_t)gr0 * CLS + col) = v0;
            *(float2*)(out + (size_t)(gr0 + 8) * CLS + col) = v1;
        }
    }
}

extern "C" void kernel_launch(void* const* d_in, const int* in_sizes, int n_in,
                              void* d_out, int out_size) {
    int iX = 0, iP = 1, iW = 2, iC = 5, iKB = 6;
    int i32[2] = {3, 4};
    int n32 = 0;
    for (int i = 0; i < n_in; i++) {
        switch (in_sizes[i]) {
            case 4194304: iX = i; break;
            case 16:      iP = i; break;
            case 512:     iW = i; break;
            case 16384:   iC = i; break;
            case 64:      iKB = i; break;
            case 32:      if (n32 < 2) i32[n32] = i; n32++; break;
            default: break;
        }
    }

    const float* X      = (const float*)d_in[iX];
    const float* phases = (const float*)d_in[iP];
    const float* w      = (const float*)d_in[iW];
    const float* cand0  = (const float*)d_in[i32[0]];
    const float* cand1  = (const float*)d_in[i32[1]];
    const float* coeff  = (const float*)d_in[iC];
    const float* kbias  = (const float*)d_in[iKB];
    float* out          = (float*)d_out;

    cudaFuncSetAttribute(qkan_mma_kernel, cudaFuncAttributeMaxDynamicSharedMemorySize,
                         SMEM_TOTAL);
    prep_b_kernel<<<1, 256>>>(coeff);
    qkan_mma_kernel<<<BATCH / TBROWS, NTHR, SMEM_TOTAL>>>(X, phases, w, cand0, cand1,
                                                          kbias, out);
}